// round 7
// baseline (speedup 1.0000x reference)
#include <cuda_runtime.h>
#include <cstdint>

// Problem constants
#define N_TOK 65536          // 16 * 4096 tokens
#define DDIM  64
#define KCODE 1024
#define TILE  64             // codebook rows per smem tile (16.5KB smem)
#define TPB   64             // threads per block in fused kernel (grid=1024 -> ~99% SM util)

// ---------------- scratch (no allocation allowed) ----------------
// cluster_sum declared as float4[] so vector atomics are provably 16B-aligned.
__device__ float4 g_cluster_sum4[KCODE * DDIM / 4];
__device__ float  g_cluster_size[KCODE];
__device__ float  g_loss;
__device__ float  g_stable[KCODE];
__device__ float  g_cnorm[KCODE];

// ---------------- packed f32x2 ops (sm_100+) ----------------
__device__ __forceinline__ float2 ffma2(float2 a, float2 b, float2 c) {
    unsigned long long au = *reinterpret_cast<unsigned long long*>(&a);
    unsigned long long bu = *reinterpret_cast<unsigned long long*>(&b);
    unsigned long long cu = *reinterpret_cast<unsigned long long*>(&c);
    unsigned long long du;
    asm("fma.rn.f32x2 %0, %1, %2, %3;" : "=l"(du) : "l"(au), "l"(bu), "l"(cu));
    return *reinterpret_cast<float2*>(&du);
}
__device__ __forceinline__ float2 fadd2(float2 a, float2 b) {
    unsigned long long au = *reinterpret_cast<unsigned long long*>(&a);
    unsigned long long bu = *reinterpret_cast<unsigned long long*>(&b);
    unsigned long long du;
    asm("add.rn.f32x2 %0, %1, %2;" : "=l"(du) : "l"(au), "l"(bu));
    return *reinterpret_cast<float2*>(&du);
}

// ---------------- kernel 1: zero accumulators + codebook norms ----------------
__global__ void prep_kernel(const float* __restrict__ cb) {
    int i = blockIdx.x * blockDim.x + threadIdx.x;
    if (i < KCODE * DDIM / 4) g_cluster_sum4[i] = make_float4(0.f, 0.f, 0.f, 0.f);
    if (i < KCODE) {
        g_cluster_size[i] = 0.0f;
        float s = 0.0f;
        const float* row = cb + i * DDIM;
        #pragma unroll 16
        for (int d = 0; d < DDIM; d++) { float v = row[d]; s = fmaf(v, v, s); }
        g_cnorm[i] = s;
    }
    if (i == 0) g_loss = 0.0f;
}

// ---------------- kernel 2 (fused): argmin + segment sums + z_q gather + loss ----------------
// dist(z,c) = ||c||^2 - 2 z.c   (||z||^2 is argmin-invariant; ordering preserved)
// smem tile holds (-2*c); accumulators seeded with ||c||^2.
// TPB=64, 1 token/thread, grid=1024: fine-grained quanta -> ~99% SM utilization,
// ~7 resident blocks/SM hide tile-load latency behind other blocks' FMA phase.
__global__ void __launch_bounds__(TPB) vq_fused_kernel(
    const float* __restrict__ z, const float* __restrict__ cb,
    float* __restrict__ idx_out, float* __restrict__ zq_out)
{
    __shared__ float4 sc4[TILE * DDIM / 4];   // -2 * codebook tile (1024 float4)
    __shared__ float  scn[TILE];              // ||c||^2 for tile
    __shared__ float  red[TPB / 32];          // loss partial per warp

    const int tok = blockIdx.x * TPB + threadIdx.x;

    // Load this thread's token: 64 f32 packed as 32 f32x2 (dim-pairs)
    float2 zp[DDIM / 2];
    {
        const float4* zf = reinterpret_cast<const float4*>(z + (size_t)tok * DDIM);
        #pragma unroll
        for (int i = 0; i < DDIM / 4; i++) {
            float4 v = zf[i];
            zp[2 * i]     = make_float2(v.x, v.y);
            zp[2 * i + 1] = make_float2(v.z, v.w);
        }
    }

    float best = 3.402823e38f;
    int   bidx = 0;

    for (int t0 = 0; t0 < KCODE; t0 += TILE) {
        __syncthreads();
        // cooperative tile load: 1024 float4 by 64 threads (16 each), scaled by -2
        {
            const float4* src = reinterpret_cast<const float4*>(cb + (size_t)t0 * DDIM);
            #pragma unroll
            for (int r = 0; r < (TILE * DDIM / 4) / TPB; r++) {
                float4 v = src[threadIdx.x + r * TPB];
                v.x *= -2.0f; v.y *= -2.0f; v.z *= -2.0f; v.w *= -2.0f;
                sc4[threadIdx.x + r * TPB] = v;
            }
            if (threadIdx.x < TILE) scn[threadIdx.x] = g_cnorm[t0 + threadIdx.x];
        }
        __syncthreads();

        #pragma unroll 4
        for (int j = 0; j < TILE; j++) {
            const float4* cp = sc4 + j * (DDIM / 4);
            float2 a0 = make_float2(scn[j], 0.f);
            float2 a1 = make_float2(0.f, 0.f), a2 = a1, a3 = a1;
            #pragma unroll
            for (int q = 0; q < DDIM / 4; q += 2) {
                float4 c0 = cp[q];
                float4 c1 = cp[q + 1];
                a0 = ffma2(zp[2 * q],     make_float2(c0.x, c0.y), a0);
                a1 = ffma2(zp[2 * q + 1], make_float2(c0.z, c0.w), a1);
                a2 = ffma2(zp[2 * q + 2], make_float2(c1.x, c1.y), a2);
                a3 = ffma2(zp[2 * q + 3], make_float2(c1.z, c1.w), a3);
            }
            a0 = fadd2(a0, a1);
            a2 = fadd2(a2, a3);
            a0 = fadd2(a0, a2);
            float s = a0.x + a0.y;   // = ||c||^2 - 2 z.c
            if (s < best) { best = s; bidx = t0 + j; }
        }
    }

    idx_out[tok] = (float)bidx;

    // histogram + vectorized segment-sum scatter (sm_90+ float4 red, 16B-aligned base)
    atomicAdd(&g_cluster_size[bidx], 1.0f);
    {
        float4* cs = g_cluster_sum4 + (size_t)bidx * (DDIM / 4);
        #pragma unroll
        for (int i = 0; i < DDIM / 4; i++) {
            atomicAdd(&cs[i], make_float4(zp[2 * i].x, zp[2 * i].y,
                                          zp[2 * i + 1].x, zp[2 * i + 1].y));
        }
    }

    // z_q gather from winning row (L2-resident cb), straight-through write + loss
    float ss = 0.0f;
    {
        const float4* qrow = reinterpret_cast<const float4*>(cb + (size_t)bidx * DDIM);
        float4* zq4 = reinterpret_cast<float4*>(zq_out + (size_t)tok * DDIM);
        #pragma unroll
        for (int i = 0; i < DDIM / 4; i++) {
            float4 q = __ldg(&qrow[i]);
            float2 za = zp[2 * i], zb = zp[2 * i + 1];
            // straight-through forward value: z + (q - z)
            zq4[i] = make_float4(za.x + (q.x - za.x), za.y + (q.y - za.y),
                                 zb.x + (q.z - zb.x), zb.y + (q.w - zb.y));
            float d0 = za.x - q.x, d1 = za.y - q.y, d2 = zb.x - q.z, d3 = zb.y - q.w;
            ss = fmaf(d0, d0, ss); ss = fmaf(d1, d1, ss);
            ss = fmaf(d2, d2, ss); ss = fmaf(d3, d3, ss);
        }
    }
    #pragma unroll
    for (int o = 16; o > 0; o >>= 1) ss += __shfl_xor_sync(0xffffffffu, ss, o);
    if ((threadIdx.x & 31) == 0) red[threadIdx.x >> 5] = ss;
    __syncthreads();
    if (threadIdx.x == 0) {
        float t = 0.0f;
        #pragma unroll
        for (int w = 0; w < TPB / 32; w++) t += red[w];
        atomicAdd(&g_loss, t);
    }
}

// ---------------- kernel 3: EMA cluster size, n, stable, loss output ----------------
__global__ void __launch_bounds__(1024) ema_a_kernel(
    const float* __restrict__ ecs_in, float* __restrict__ out_ecs,
    float* __restrict__ out_loss)
{
    const int k = threadIdx.x;
    const float necs = ecs_in[k] * 0.99f + 0.01f * g_cluster_size[k];
    out_ecs[k] = necs;

    // block-wide sum over 1024 values
    float s = necs;
    #pragma unroll
    for (int o = 16; o > 0; o >>= 1) s += __shfl_xor_sync(0xffffffffu, s, o);
    __shared__ float red[32];
    __shared__ float n_sh;
    if ((k & 31) == 0) red[k >> 5] = s;
    __syncthreads();
    if (k < 32) {
        float t = red[k];
        #pragma unroll
        for (int o = 16; o > 0; o >>= 1) t += __shfl_xor_sync(0xffffffffu, t, o);
        if (k == 0) n_sh = t;
    }
    __syncthreads();
    const float n = n_sh;
    g_stable[k] = (necs + 1e-5f) / (n + (float)KCODE * 1e-5f) * n;

    if (k == 0) out_loss[0] = 0.25f * g_loss * (1.0f / 4194304.0f);
}

// ---------------- kernel 4: new_ew + new_codebook ----------------
__global__ void __launch_bounds__(256) ema_b_kernel(
    const float* __restrict__ ema_w, float* __restrict__ out_cb,
    float* __restrict__ out_ew)
{
    const int i = blockIdx.x * 256 + threadIdx.x;   // over KCODE*DDIM
    const int k = i >> 6;
    const float cs = reinterpret_cast<const float*>(g_cluster_sum4)[i];
    const float ew = ema_w[i] * 0.99f + 0.01f * cs;
    out_ew[i] = ew;
    out_cb[i] = ew / g_stable[k];
}

// ---------------- launch ----------------
extern "C" void kernel_launch(void* const* d_in, const int* in_sizes, int n_in,
                              void* d_out, int out_size)
{
    (void)in_sizes; (void)n_in; (void)out_size;
    const float* z   = (const float*)d_in[0];   // [16,4096,64]
    const float* cb  = (const float*)d_in[1];   // [1024,64]
    const float* ecs = (const float*)d_in[2];   // [1024]
    const float* ew  = (const float*)d_in[3];   // [1024,64]

    float* out    = (float*)d_out;
    float* o_zq   = out;                        // 4194304
    float* o_loss = o_zq + N_TOK * DDIM;        // 1
    float* o_idx  = o_loss + 1;                 // 65536
    float* o_cb   = o_idx + N_TOK;              // 65536
    float* o_ecs  = o_cb + KCODE * DDIM;        // 1024
    float* o_ew   = o_ecs + KCODE;              // 65536

    prep_kernel<<<(KCODE * DDIM + 255) / 256, 256>>>(cb);
    vq_fused_kernel<<<N_TOK / TPB, TPB>>>(z, cb, o_idx, o_zq);
    ema_a_kernel<<<1, 1024>>>(ecs, o_ecs, o_loss);
    ema_b_kernel<<<(KCODE * DDIM) / 256, 256>>>(ew, o_cb, o_ew);
}

// round 8
// speedup vs baseline: 1.1356x; 1.1356x over previous
#include <cuda_runtime.h>
#include <cstdint>

// Problem constants
#define N_TOK 65536          // 16 * 4096 tokens
#define DDIM  64
#define KCODE 1024
#define TILE  64             // codebook rows per smem tile (16.5KB smem)
#define TPB   32             // 1 warp per block
#define TOKPT 2              // tokens per thread -> 16 LDS feed 64 ffma2 per code

// ---------------- scratch (no allocation allowed) ----------------
__device__ float4 g_cluster_sum4[KCODE * DDIM / 4];  // float4[] => 16B-aligned atomics
__device__ float  g_cluster_size[KCODE];
__device__ float  g_loss;
__device__ float  g_stable[KCODE];
__device__ float  g_cnorm[KCODE];

// ---------------- packed f32x2 ops (sm_100+) ----------------
__device__ __forceinline__ float2 ffma2(float2 a, float2 b, float2 c) {
    unsigned long long au = *reinterpret_cast<unsigned long long*>(&a);
    unsigned long long bu = *reinterpret_cast<unsigned long long*>(&b);
    unsigned long long cu = *reinterpret_cast<unsigned long long*>(&c);
    unsigned long long du;
    asm("fma.rn.f32x2 %0, %1, %2, %3;" : "=l"(du) : "l"(au), "l"(bu), "l"(cu));
    return *reinterpret_cast<float2*>(&du);
}
__device__ __forceinline__ float2 fadd2(float2 a, float2 b) {
    unsigned long long au = *reinterpret_cast<unsigned long long*>(&a);
    unsigned long long bu = *reinterpret_cast<unsigned long long*>(&b);
    unsigned long long du;
    asm("add.rn.f32x2 %0, %1, %2;" : "=l"(du) : "l"(au), "l"(bu));
    return *reinterpret_cast<float2*>(&du);
}

// ---------------- kernel 1: zero accumulators + codebook norms ----------------
__global__ void prep_kernel(const float* __restrict__ cb) {
    int i = blockIdx.x * blockDim.x + threadIdx.x;
    if (i < KCODE * DDIM / 4) g_cluster_sum4[i] = make_float4(0.f, 0.f, 0.f, 0.f);
    if (i < KCODE) {
        g_cluster_size[i] = 0.0f;
        float s = 0.0f;
        const float* row = cb + i * DDIM;
        #pragma unroll 16
        for (int d = 0; d < DDIM; d++) { float v = row[d]; s = fmaf(v, v, s); }
        g_cnorm[i] = s;
    }
    if (i == 0) g_loss = 0.0f;
}

// ---------------- kernel 2 (fused): argmin + segment sums + z_q gather + loss ----------------
// dist(z,c) = ||c||^2 - 2 z.c   (||z||^2 argmin-invariant; ordering preserved)
// smem tile holds (-2*c); accumulators seeded with ||c||^2.
// TPB=32, TOKPT=2, grid=1024: 98.9% SM quanta utilization, and each 16-LDS code
// read feeds 64 ffma2 so the smem crossbar (eff-4 cyc LDS) sits at half the FMA time.
__global__ void __launch_bounds__(TPB) vq_fused_kernel(
    const float* __restrict__ z, const float* __restrict__ cb,
    float* __restrict__ idx_out, float* __restrict__ zq_out)
{
    __shared__ float4 sc4[TILE * DDIM / 4];   // -2 * codebook tile (1024 float4)
    __shared__ float  scn[TILE];              // ||c||^2 for tile

    const int tok0 = blockIdx.x * (TPB * TOKPT) + threadIdx.x;   // token A
    const int tok1 = tok0 + TPB;                                  // token B

    // Load both tokens: 64 f32 each, packed as 32 f32x2 (dim-pairs)
    float2 zA[DDIM / 2], zB[DDIM / 2];
    {
        const float4* fA = reinterpret_cast<const float4*>(z + (size_t)tok0 * DDIM);
        const float4* fB = reinterpret_cast<const float4*>(z + (size_t)tok1 * DDIM);
        #pragma unroll
        for (int i = 0; i < DDIM / 4; i++) {
            float4 a = fA[i], b = fB[i];
            zA[2 * i] = make_float2(a.x, a.y); zA[2 * i + 1] = make_float2(a.z, a.w);
            zB[2 * i] = make_float2(b.x, b.y); zB[2 * i + 1] = make_float2(b.z, b.w);
        }
    }

    float bestA = 3.402823e38f, bestB = 3.402823e38f;
    int   idxA = 0, idxB = 0;

    for (int t0 = 0; t0 < KCODE; t0 += TILE) {
        __syncthreads();
        // cooperative tile load: 1024 float4 by 32 threads (32 each), scaled by -2
        {
            const float4* src = reinterpret_cast<const float4*>(cb + (size_t)t0 * DDIM);
            #pragma unroll
            for (int r = 0; r < (TILE * DDIM / 4) / TPB; r++) {
                float4 v = src[threadIdx.x + r * TPB];
                v.x *= -2.0f; v.y *= -2.0f; v.z *= -2.0f; v.w *= -2.0f;
                sc4[threadIdx.x + r * TPB] = v;
            }
            scn[threadIdx.x]       = g_cnorm[t0 + threadIdx.x];
            scn[threadIdx.x + 32]  = g_cnorm[t0 + threadIdx.x + 32];
        }
        __syncthreads();

        #pragma unroll 2
        for (int j = 0; j < TILE; j++) {
            const float4* cp = sc4 + j * (DDIM / 4);
            const float cn = scn[j];
            float2 a0 = make_float2(cn, 0.f), a1 = make_float2(0.f, 0.f), a2 = a1, a3 = a1;
            float2 b0 = make_float2(cn, 0.f), b1 = a1, b2 = a1, b3 = a1;
            #pragma unroll
            for (int q = 0; q < DDIM / 4; q += 2) {
                float4 c0 = cp[q];
                float2 lo0 = make_float2(c0.x, c0.y), hi0 = make_float2(c0.z, c0.w);
                a0 = ffma2(zA[2 * q],     lo0, a0);
                a1 = ffma2(zA[2 * q + 1], hi0, a1);
                b0 = ffma2(zB[2 * q],     lo0, b0);
                b1 = ffma2(zB[2 * q + 1], hi0, b1);
                float4 c1 = cp[q + 1];
                float2 lo1 = make_float2(c1.x, c1.y), hi1 = make_float2(c1.z, c1.w);
                a2 = ffma2(zA[2 * q + 2], lo1, a2);
                a3 = ffma2(zA[2 * q + 3], hi1, a3);
                b2 = ffma2(zB[2 * q + 2], lo1, b2);
                b3 = ffma2(zB[2 * q + 3], hi1, b3);
            }
            a0 = fadd2(a0, a1); a2 = fadd2(a2, a3); a0 = fadd2(a0, a2);
            b0 = fadd2(b0, b1); b2 = fadd2(b2, b3); b0 = fadd2(b0, b2);
            float sA = a0.x + a0.y;   // = ||c||^2 - 2 zA.c
            float sB = b0.x + b0.y;
            if (sA < bestA) { bestA = sA; idxA = t0 + j; }
            if (sB < bestB) { bestB = sB; idxB = t0 + j; }
        }
    }

    idx_out[tok0] = (float)idxA;
    idx_out[tok1] = (float)idxB;

    // histogram + vectorized segment-sum scatter (sm_90+ float4 red, 16B-aligned base)
    atomicAdd(&g_cluster_size[idxA], 1.0f);
    atomicAdd(&g_cluster_size[idxB], 1.0f);
    {
        float4* csA = g_cluster_sum4 + (size_t)idxA * (DDIM / 4);
        float4* csB = g_cluster_sum4 + (size_t)idxB * (DDIM / 4);
        #pragma unroll
        for (int i = 0; i < DDIM / 4; i++) {
            atomicAdd(&csA[i], make_float4(zA[2 * i].x, zA[2 * i].y, zA[2 * i + 1].x, zA[2 * i + 1].y));
            atomicAdd(&csB[i], make_float4(zB[2 * i].x, zB[2 * i].y, zB[2 * i + 1].x, zB[2 * i + 1].y));
        }
    }

    // z_q gather from winning rows (L2-resident cb), straight-through write + loss
    float ss = 0.0f;
    {
        const float4* qA = reinterpret_cast<const float4*>(cb + (size_t)idxA * DDIM);
        float4* oA = reinterpret_cast<float4*>(zq_out + (size_t)tok0 * DDIM);
        #pragma unroll
        for (int i = 0; i < DDIM / 4; i++) {
            float4 q = __ldg(&qA[i]);
            float2 za = zA[2 * i], zb = zA[2 * i + 1];
            oA[i] = make_float4(za.x + (q.x - za.x), za.y + (q.y - za.y),
                                zb.x + (q.z - zb.x), zb.y + (q.w - zb.y));
            float d0 = za.x - q.x, d1 = za.y - q.y, d2 = zb.x - q.z, d3 = zb.y - q.w;
            ss = fmaf(d0, d0, ss); ss = fmaf(d1, d1, ss);
            ss = fmaf(d2, d2, ss); ss = fmaf(d3, d3, ss);
        }
        const float4* qB = reinterpret_cast<const float4*>(cb + (size_t)idxB * DDIM);
        float4* oB = reinterpret_cast<float4*>(zq_out + (size_t)tok1 * DDIM);
        #pragma unroll
        for (int i = 0; i < DDIM / 4; i++) {
            float4 q = __ldg(&qB[i]);
            float2 za = zB[2 * i], zb = zB[2 * i + 1];
            oB[i] = make_float4(za.x + (q.x - za.x), za.y + (q.y - za.y),
                                zb.x + (q.z - zb.x), zb.y + (q.w - zb.y));
            float d0 = za.x - q.x, d1 = za.y - q.y, d2 = zb.x - q.z, d3 = zb.y - q.w;
            ss = fmaf(d0, d0, ss); ss = fmaf(d1, d1, ss);
            ss = fmaf(d2, d2, ss); ss = fmaf(d3, d3, ss);
        }
    }
    // single-warp block: warp reduction then one atomic
    #pragma unroll
    for (int o = 16; o > 0; o >>= 1) ss += __shfl_xor_sync(0xffffffffu, ss, o);
    if (threadIdx.x == 0) atomicAdd(&g_loss, ss);
}

// ---------------- kernel 3: EMA cluster size, n, stable, loss output ----------------
__global__ void __launch_bounds__(1024) ema_a_kernel(
    const float* __restrict__ ecs_in, float* __restrict__ out_ecs,
    float* __restrict__ out_loss)
{
    const int k = threadIdx.x;
    const float necs = ecs_in[k] * 0.99f + 0.01f * g_cluster_size[k];
    out_ecs[k] = necs;

    // block-wide sum over 1024 values
    float s = necs;
    #pragma unroll
    for (int o = 16; o > 0; o >>= 1) s += __shfl_xor_sync(0xffffffffu, s, o);
    __shared__ float red[32];
    __shared__ float n_sh;
    if ((k & 31) == 0) red[k >> 5] = s;
    __syncthreads();
    if (k < 32) {
        float t = red[k];
        #pragma unroll
        for (int o = 16; o > 0; o >>= 1) t += __shfl_xor_sync(0xffffffffu, t, o);
        if (k == 0) n_sh = t;
    }
    __syncthreads();
    const float n = n_sh;
    g_stable[k] = (necs + 1e-5f) / (n + (float)KCODE * 1e-5f) * n;

    if (k == 0) out_loss[0] = 0.25f * g_loss * (1.0f / 4194304.0f);
}

// ---------------- kernel 4: new_ew + new_codebook ----------------
__global__ void __launch_bounds__(256) ema_b_kernel(
    const float* __restrict__ ema_w, float* __restrict__ out_cb,
    float* __restrict__ out_ew)
{
    const int i = blockIdx.x * 256 + threadIdx.x;   // over KCODE*DDIM
    const int k = i >> 6;
    const float cs = reinterpret_cast<const float*>(g_cluster_sum4)[i];
    const float ew = ema_w[i] * 0.99f + 0.01f * cs;
    out_ew[i] = ew;
    out_cb[i] = ew / g_stable[k];
}

// ---------------- launch ----------------
extern "C" void kernel_launch(void* const* d_in, const int* in_sizes, int n_in,
                              void* d_out, int out_size)
{
    (void)in_sizes; (void)n_in; (void)out_size;
    const float* z   = (const float*)d_in[0];   // [16,4096,64]
    const float* cb  = (const float*)d_in[1];   // [1024,64]
    const float* ecs = (const float*)d_in[2];   // [1024]
    const float* ew  = (const float*)d_in[3];   // [1024,64]

    float* out    = (float*)d_out;
    float* o_zq   = out;                        // 4194304
    float* o_loss = o_zq + N_TOK * DDIM;        // 1
    float* o_idx  = o_loss + 1;                 // 65536
    float* o_cb   = o_idx + N_TOK;              // 65536
    float* o_ecs  = o_cb + KCODE * DDIM;        // 1024
    float* o_ew   = o_ecs + KCODE;              // 65536

    prep_kernel<<<(KCODE * DDIM + 255) / 256, 256>>>(cb);
    vq_fused_kernel<<<N_TOK / (TPB * TOKPT), TPB>>>(z, cb, o_idx, o_zq);
    ema_a_kernel<<<1, 1024>>>(ecs, o_ecs, o_loss);
    ema_b_kernel<<<(KCODE * DDIM) / 256, 256>>>(ew, o_cb, o_ew);
}

// round 14
// speedup vs baseline: 2.0727x; 1.8252x over previous
#include <cuda_runtime.h>
#include <cstdint>

// Problem constants
#define N_TOK  65536
#define DDIM   64
#define KCODE  1024
#define TILE   128           // codes per smem tile
#define TPB    64            // threads per block, 1 token/thread, grid=1024
#define RING   64            // candidate ring slots per thread

// int8 quantization: scale 127/5 (clamp at 5 sigma)
#define QS      (127.0f / 5.0f)
#define DEQ2    (2.0f * (5.0f / 127.0f) * (5.0f / 127.0f))   // dist = cn - DEQ2*dotq
#define INV_DEQ (1.0f / DEQ2)
#define MARGIN_UNITS 1400    // 4.34 fp32 units ~= 9.6 sigma of quantization error

// ---------------- scratch (no allocation allowed) ----------------
__device__ float4 g_cluster_sum4[KCODE * DDIM / 4];
__device__ float  g_cluster_size[KCODE];
__device__ float  g_loss;
__device__ float  g_stable[KCODE];
__device__ float  g_cnorm[KCODE];
__device__ int    g_cnormi[KCODE];          // round(cnorm / DEQ2)
__device__ int4   g_cb8[KCODE * 4];         // int8-packed codebook, 4 int4 per row

__device__ __forceinline__ int q8(float v) {
    int q = __float2int_rn(v * QS);
    return q > 127 ? 127 : (q < -127 ? -127 : q);
}

// exact fp32 distance of one code row vs registered z
__device__ __forceinline__ float exact_dist(const float* __restrict__ cb,
                                            const float4* zr, int j) {
    const float4* c4 = reinterpret_cast<const float4*>(cb + (size_t)j * DDIM);
    float s0 = 0.f, s1 = 0.f, s2 = 0.f, s3 = 0.f;
    #pragma unroll
    for (int i = 0; i < 16; i++) {
        float4 c = __ldg(&c4[i]);
        float4 zz = zr[i];
        s0 = fmaf(zz.x, c.x, s0); s1 = fmaf(zz.y, c.y, s1);
        s2 = fmaf(zz.z, c.z, s2); s3 = fmaf(zz.w, c.w, s3);
    }
    return fmaf(-2.0f, (s0 + s1) + (s2 + s3), __ldg(&g_cnorm[j]));
}

// ---------------- kernel 1: zero accumulators + codebook quantization + norms ----------------
__global__ void prep_kernel(const float* __restrict__ cb) {
    int i = blockIdx.x * blockDim.x + threadIdx.x;
    if (i < KCODE * DDIM / 4) g_cluster_sum4[i] = make_float4(0.f, 0.f, 0.f, 0.f);
    if (i < KCODE) {
        g_cluster_size[i] = 0.0f;
        float s = 0.0f;
        const float4* row4 = reinterpret_cast<const float4*>(cb + i * DDIM);
        #pragma unroll
        for (int g = 0; g < 4; g++) {
            int w[4];
            #pragma unroll
            for (int k = 0; k < 4; k++) {
                float4 v = row4[g * 4 + k];
                s = fmaf(v.x, v.x, s); s = fmaf(v.y, v.y, s);
                s = fmaf(v.z, v.z, s); s = fmaf(v.w, v.w, s);
                w[k] = (q8(v.x) & 255) | ((q8(v.y) & 255) << 8)
                     | ((q8(v.z) & 255) << 16) | ((q8(v.w) & 255) << 24);
            }
            g_cb8[i * 4 + g] = make_int4(w[0], w[1], w[2], w[3]);
        }
        g_cnorm[i]  = s;
        g_cnormi[i] = __float2int_rn(s * INV_DEQ);
    }
    if (i == 0) g_loss = 0.0f;
}

// ---------------- kernel 2: int8 dp4a screen + exact recheck + full VQ epilogue ----------------
__global__ void __launch_bounds__(TPB) vq_screen_kernel(
    const float* __restrict__ z, const float* __restrict__ cb,
    float* __restrict__ idx_out, float* __restrict__ zq_out)
{
    __shared__ int4     tile8[TILE * 4];      // 8KB int8 codebook tile
    __shared__ int      tnormi[TILE];         // quantized-units norms
    __shared__ uint32_t ring[TPB * RING];     // 16KB candidate ring
    __shared__ float    red[TPB / 32];

    const int tid = threadIdx.x;
    const int tok = blockIdx.x * TPB + tid;
    const float4* zf = reinterpret_cast<const float4*>(z + (size_t)tok * DDIM);

    // quantize own token to packed int8 (z fp32 reloaded later in epilogue)
    int zq8[16];
    #pragma unroll
    for (int i = 0; i < 16; i++) {
        float4 v = __ldg(&zf[i]);
        zq8[i] = (q8(v.x) & 255) | ((q8(v.y) & 255) << 8)
               | ((q8(v.z) & 255) << 16) | ((q8(v.w) & 255) << 24);
    }

    int bestu = 1 << 24;
    int thru  = 1 << 24;
    int cnt   = 0;
    uint32_t* myring = ring + tid * RING;

    for (int t0 = 0; t0 < KCODE; t0 += TILE) {
        __syncthreads();
        {   // cooperative tile load: 512 int4 by 64 threads
            const int4* src = g_cb8 + t0 * 4;
            #pragma unroll
            for (int r = 0; r < (TILE * 4) / TPB; r++)
                tile8[tid + r * TPB] = __ldg(&src[tid + r * TPB]);
            tnormi[tid]       = g_cnormi[t0 + tid];
            tnormi[tid + 64]  = g_cnormi[t0 + tid + 64];
        }
        __syncthreads();

        #pragma unroll 4
        for (int j = 0; j < TILE; j++) {
            const int4* cp = tile8 + j * 4;
            int4 c0 = cp[0], c1 = cp[1], c2 = cp[2], c3 = cp[3];
            int a0 = 0, a1 = 0, a2 = 0, a3 = 0;
            a0 = __dp4a(c0.x, zq8[0], a0);  a1 = __dp4a(c0.y, zq8[1], a1);
            a2 = __dp4a(c0.z, zq8[2], a2);  a3 = __dp4a(c0.w, zq8[3], a3);
            a0 = __dp4a(c1.x, zq8[4], a0);  a1 = __dp4a(c1.y, zq8[5], a1);
            a2 = __dp4a(c1.z, zq8[6], a2);  a3 = __dp4a(c1.w, zq8[7], a3);
            a0 = __dp4a(c2.x, zq8[8], a0);  a1 = __dp4a(c2.y, zq8[9], a1);
            a2 = __dp4a(c2.z, zq8[10], a2); a3 = __dp4a(c2.w, zq8[11], a3);
            a0 = __dp4a(c3.x, zq8[12], a0); a1 = __dp4a(c3.y, zq8[13], a1);
            a2 = __dp4a(c3.z, zq8[14], a2); a3 = __dp4a(c3.w, zq8[15], a3);
            int du = tnormi[j] - ((a0 + a1) + (a2 + a3));   // approx dist in units
            if (du < thru) {
                myring[cnt & (RING - 1)] =
                    ((uint32_t)(du + (1 << 18)) << 10) | (uint32_t)(t0 + j);
                cnt++;
            }
            if (du < bestu) { bestu = du; thru = du + MARGIN_UNITS; }
        }
    }

    // reload z fp32 for exact eval + epilogue
    float4 zr[16];
    #pragma unroll
    for (int i = 0; i < 16; i++) zr[i] = __ldg(&zf[i]);

    int ei;
    if (cnt > RING) {
        // ring overflowed (vanishingly rare): full exact scan, ascending j (first-min tiebreak)
        float eb = 3.402823e38f; ei = 0;
        for (int j = 0; j < KCODE; j++) {
            float d = exact_dist(cb, zr, j);
            if (d < eb) { eb = d; ei = j; }
        }
    } else {
        // exact recheck among in-margin candidates (ascending insertion order)
        const int thr_final = bestu + MARGIN_UNITS;
        int npass = 0, only_j = 0;
        for (int e = 0; e < cnt; e++) {
            uint32_t key = myring[e];
            int du = (int)(key >> 10) - (1 << 18);
            if (du < thr_final) { npass++; only_j = (int)(key & 1023u); }
        }
        if (npass == 1) {
            ei = only_j;    // unique in-margin candidate: approx argmin is exact
        } else {
            float eb = 3.402823e38f; ei = 0;
            for (int e = 0; e < cnt; e++) {
                uint32_t key = myring[e];
                int du = (int)(key >> 10) - (1 << 18);
                if (du < thr_final) {
                    int j = (int)(key & 1023u);
                    float d = exact_dist(cb, zr, j);
                    if (d < eb) { eb = d; ei = j; }
                }
            }
        }
    }

    // ---- VQ epilogue (identical to validated fp32 kernel) ----
    idx_out[tok] = (float)ei;
    atomicAdd(&g_cluster_size[ei], 1.0f);
    {
        float4* cs = g_cluster_sum4 + (size_t)ei * (DDIM / 4);
        #pragma unroll
        for (int i = 0; i < DDIM / 4; i++) atomicAdd(&cs[i], zr[i]);
    }
    float ss = 0.0f;
    {
        const float4* qrow = reinterpret_cast<const float4*>(cb + (size_t)ei * DDIM);
        float4* zq4 = reinterpret_cast<float4*>(zq_out + (size_t)tok * DDIM);
        #pragma unroll
        for (int i = 0; i < DDIM / 4; i++) {
            float4 q = __ldg(&qrow[i]);
            float4 zz = zr[i];
            zq4[i] = make_float4(zz.x + (q.x - zz.x), zz.y + (q.y - zz.y),
                                 zz.z + (q.z - zz.z), zz.w + (q.w - zz.w));
            float d0 = zz.x - q.x, d1 = zz.y - q.y, d2 = zz.z - q.z, d3 = zz.w - q.w;
            ss = fmaf(d0, d0, ss); ss = fmaf(d1, d1, ss);
            ss = fmaf(d2, d2, ss); ss = fmaf(d3, d3, ss);
        }
    }
    #pragma unroll
    for (int o = 16; o > 0; o >>= 1) ss += __shfl_xor_sync(0xffffffffu, ss, o);
    if ((tid & 31) == 0) red[tid >> 5] = ss;
    __syncthreads();
    if (tid == 0) {
        float t = 0.0f;
        #pragma unroll
        for (int w = 0; w < TPB / 32; w++) t += red[w];
        atomicAdd(&g_loss, t);
    }
}

// ---------------- kernel 3: EMA cluster size, n, stable, loss output ----------------
__global__ void __launch_bounds__(1024) ema_a_kernel(
    const float* __restrict__ ecs_in, float* __restrict__ out_ecs,
    float* __restrict__ out_loss)
{
    const int k = threadIdx.x;
    const float necs = ecs_in[k] * 0.99f + 0.01f * g_cluster_size[k];
    out_ecs[k] = necs;
    float s = necs;
    #pragma unroll
    for (int o = 16; o > 0; o >>= 1) s += __shfl_xor_sync(0xffffffffu, s, o);
    __shared__ float red[32];
    __shared__ float n_sh;
    if ((k & 31) == 0) red[k >> 5] = s;
    __syncthreads();
    if (k < 32) {
        float t = red[k];
        #pragma unroll
        for (int o = 16; o > 0; o >>= 1) t += __shfl_xor_sync(0xffffffffu, t, o);
        if (k == 0) n_sh = t;
    }
    __syncthreads();
    const float n = n_sh;
    g_stable[k] = (necs + 1e-5f) / (n + (float)KCODE * 1e-5f) * n;
    if (k == 0) out_loss[0] = 0.25f * g_loss * (1.0f / 4194304.0f);
}

// ---------------- kernel 4: new_ew + new_codebook ----------------
__global__ void __launch_bounds__(256) ema_b_kernel(
    const float* __restrict__ ema_w, float* __restrict__ out_cb,
    float* __restrict__ out_ew)
{
    const int i = blockIdx.x * 256 + threadIdx.x;
    const int k = i >> 6;
    const float cs = reinterpret_cast<const float*>(g_cluster_sum4)[i];
    const float ew = ema_w[i] * 0.99f + 0.01f * cs;
    out_ew[i] = ew;
    out_cb[i] = ew / g_stable[k];
}

// ---------------- launch ----------------
extern "C" void kernel_launch(void* const* d_in, const int* in_sizes, int n_in,
                              void* d_out, int out_size)
{
    (void)in_sizes; (void)n_in; (void)out_size;
    const float* z   = (const float*)d_in[0];   // [16,4096,64]
    const float* cb  = (const float*)d_in[1];   // [1024,64]
    const float* ecs = (const float*)d_in[2];   // [1024]
    const float* ew  = (const float*)d_in[3];   // [1024,64]

    float* out    = (float*)d_out;
    float* o_zq   = out;                        // 4194304
    float* o_loss = o_zq + N_TOK * DDIM;        // 1
    float* o_idx  = o_loss + 1;                 // 65536
    float* o_cb   = o_idx + N_TOK;              // 65536
    float* o_ecs  = o_cb + KCODE * DDIM;        // 1024
    float* o_ew   = o_ecs + KCODE;              // 65536

    prep_kernel<<<64, 256>>>(cb);
    vq_screen_kernel<<<N_TOK / TPB, TPB>>>(z, cb, o_idx, o_zq);
    ema_a_kernel<<<1, 1024>>>(ecs, o_ecs, o_loss);
    ema_b_kernel<<<(KCODE * DDIM) / 256, 256>>>(ew, o_cb, o_ew);
}